// round 15
// baseline (speedup 1.0000x reference)
#include <cuda_runtime.h>
#include <cuda_bf16.h>
#include <cuda_fp16.h>
#include <cstddef>
#include <cstdint>

// Problem dims (fixed)
#define B_   256
#define T_   512
#define IN_  128
#define H_   256
#define W1_  512
#define W2_  512
#define BT_  (B_ * T_)   // 131072

// ---------------------------------------------------------------------------
// Scratch (device globals — no allocations allowed anywhere)
// ---------------------------------------------------------------------------
__device__ float g_aw [(size_t)BT_ * H_];   // Phase C attention logits
__device__ float g_xin[(size_t)BT_ * H_];   // input-MLP output, layout [T, B, H]
__device__ float g_hs [(size_t)BT_ * H_];   // all hidden states,  layout [T, B, H]
// bf16 hi/lo split operands (Phase A GEMMs; a2* reused for Phase C hs-split)
__device__ __nv_bfloat16 g_xhi [(size_t)BT_ * IN_],  g_xlo [(size_t)BT_ * IN_];
__device__ __nv_bfloat16 g_a1hi[(size_t)BT_ * W1_],  g_a1lo[(size_t)BT_ * W1_];
__device__ __nv_bfloat16 g_a2hi[(size_t)BT_ * W2_],  g_a2lo[(size_t)BT_ * W2_];
__device__ __nv_bfloat16 g_w1Thi[W1_ * IN_], g_w1Tlo[W1_ * IN_];  // also att_w (256*256)
__device__ __nv_bfloat16 g_w2Thi[W2_ * W1_], g_w2Tlo[W2_ * W1_];
__device__ __nv_bfloat16 g_w3Thi[H_  * W2_], g_w3Tlo[H_  * W2_];
// fp16 recurrence weights (Phase B stream — halves smem crossbar traffic)
__device__ __half g_w1h[H_ * W1_];
__device__ __half g_w2h[W1_ * W2_];
__device__ __half g_w3h[W2_ * H_];

// ---------------------------------------------------------------------------
// helpers
// ---------------------------------------------------------------------------
typedef unsigned long long u64;

__device__ __forceinline__ u64 fma2(u64 a, u64 b, u64 c) {
    u64 d;
    asm("fma.rn.f32x2 %0, %1, %2, %3;" : "=l"(d) : "l"(a), "l"(b), "l"(c));
    return d;
}
__device__ __forceinline__ u64 dup2(float x) {
    u64 d; unsigned int u = __float_as_uint(x);
    asm("mov.b64 %0, {%1, %1};" : "=l"(d) : "r"(u));
    return d;
}
__device__ __forceinline__ void unpack2(u64 v, float& lo, float& hi) {
    unsigned int a, b;
    asm("mov.b64 {%0, %1}, %2;" : "=r"(a), "=r"(b) : "l"(v));
    lo = __uint_as_float(a); hi = __uint_as_float(b);
}
__device__ __forceinline__ uint32_t smem_u32(const void* p) {
    uint32_t a;
    asm("{ .reg .u64 t; cvta.to.shared.u64 t, %1; cvt.u32.u64 %0, t; }"
        : "=r"(a) : "l"(p));
    return a;
}
__device__ __forceinline__ void mbar_init(uint32_t mbar, uint32_t count) {
    asm volatile("mbarrier.init.shared.b64 [%0], %1;" :: "r"(mbar), "r"(count) : "memory");
}
__device__ __forceinline__ void mbar_expect_tx(uint32_t mbar, uint32_t bytes) {
    asm volatile("mbarrier.arrive.expect_tx.shared.b64 _, [%0], %1;"
                 :: "r"(mbar), "r"(bytes) : "memory");
}
__device__ __forceinline__ void mbar_wait_parity(uint32_t mbar, uint32_t parity) {
    asm volatile(
        "{\n\t"
        ".reg .pred P;\n\t"
        "WAIT_%=:\n\t"
        "mbarrier.try_wait.parity.shared.b64 P, [%0], %1, 0x989680;\n\t"
        "@P bra.uni DONE_%=;\n\t"
        "bra.uni WAIT_%=;\n\t"
        "DONE_%=:\n\t"
        "}"
        :: "r"(mbar), "r"(parity) : "memory");
}
__device__ __forceinline__ uint32_t mapa_rank(uint32_t addr, uint32_t rank) {
    uint32_t r;
    asm("mapa.shared::cluster.u32 %0, %1, %2;" : "=r"(r) : "r"(addr), "r"(rank));
    return r;
}
__device__ __forceinline__ void mbar_arrive_remote(uint32_t cluster_addr) {
    asm volatile("mbarrier.arrive.shared::cluster.b64 _, [%0];"
                 :: "r"(cluster_addr) : "memory");
}
__device__ __forceinline__ void bulk_g2s_mc(uint32_t dst_smem, const void* src_gmem,
                                            uint32_t bytes, uint32_t mbar, uint16_t mask) {
    asm volatile(
        "cp.async.bulk.shared::cluster.global.mbarrier::complete_tx::bytes.multicast::cluster "
        "[%0], [%1], %2, [%3], %4;"
        :: "r"(dst_smem), "l"(src_gmem), "r"(bytes), "r"(mbar), "h"(mask) : "memory");
}
__device__ __forceinline__ uint32_t cluster_rank() {
    uint32_t r; asm("mov.u32 %0, %%cluster_ctarank;" : "=r"(r)); return r;
}
#define CLUSTER_SYNC() do { \
    asm volatile("barrier.cluster.arrive.aligned;" ::: "memory"); \
    asm volatile("barrier.cluster.wait.aligned;"   ::: "memory"); \
} while (0)

__device__ __forceinline__ void cp16(uint32_t dst, const void* src) {
    asm volatile("cp.async.cg.shared.global [%0], [%1], 16;" :: "r"(dst), "l"(src));
}

// ---------------------------------------------------------------------------
// bf16 hi/lo split helpers + kernels (Phase A / C)
// ---------------------------------------------------------------------------
__device__ __forceinline__ void split_bf16(float v, __nv_bfloat16& h, __nv_bfloat16& l) {
    h = __float2bfloat16(v);
    l = __float2bfloat16(v - __bfloat162float(h));
}

__global__ void split_kernel(const float* __restrict__ in, __nv_bfloat16* __restrict__ hi,
                             __nv_bfloat16* __restrict__ lo, int n)
{
    int i = (blockIdx.x * 256 + threadIdx.x) * 4;
    if (i >= n) return;
    float4 v = *(const float4*)(in + i);
    __nv_bfloat16 h0, l0, h1, l1, h2, l2, h3, l3;
    split_bf16(v.x, h0, l0); split_bf16(v.y, h1, l1);
    split_bf16(v.z, h2, l2); split_bf16(v.w, h3, l3);
    __nv_bfloat162 hp0 = {h0, h1}, hp1 = {h2, h3}, lp0 = {l0, l1}, lp1 = {l2, l3};
    *(uint2*)(hi + i) = make_uint2(*(uint32_t*)&hp0, *(uint32_t*)&hp1);
    *(uint2*)(lo + i) = make_uint2(*(uint32_t*)&lp0, *(uint32_t*)&lp1);
}

// in: [Kd, Nd] row-major -> out transposed [Nd, Kd] hi/lo bf16
__global__ void splitT_kernel(const float* __restrict__ in, __nv_bfloat16* __restrict__ hiT,
                              __nv_bfloat16* __restrict__ loT, int Kd, int Nd)
{
    int idx = blockIdx.x * 256 + threadIdx.x;
    if (idx >= Kd * Nd) return;
    int k = idx / Nd, n2 = idx - k * Nd;
    __nv_bfloat16 h, l;
    split_bf16(in[idx], h, l);
    hiT[(size_t)n2 * Kd + k] = h;
    loT[(size_t)n2 * Kd + k] = l;
}

// fp32 -> fp16 (RN) for Phase B weight stream
__global__ void to_half_kernel(const float* __restrict__ in, __half* __restrict__ out, int n)
{
    int i = (blockIdx.x * 256 + threadIdx.x) * 4;
    if (i >= n) return;
    float4 v = *(const float4*)(in + i);
    __half2 p0 = __floats2half2_rn(v.x, v.y);
    __half2 p1 = __floats2half2_rn(v.z, v.w);
    *(uint2*)(out + i) = make_uint2(*(uint32_t*)&p0, *(uint32_t*)&p1);
}

// ---------------------------------------------------------------------------
// bf16-split GEMM via mma.sync (m16n8k16) with 2-stage cp.async pipeline.
// (verified Round 14 — UNCHANGED)
// ---------------------------------------------------------------------------
#define PADK 40
#define ROWB (PADK * 2)
#define TILE_B (128 * ROWB)
#define STAGE_B (4 * TILE_B)
#define MMA_SMEM (2 * STAGE_B)   // 81920

template <int ACT, int OUT>
__global__ void __launch_bounds__(256)
mm_mma_kernel(const __nv_bfloat16* __restrict__ Ahi, const __nv_bfloat16* __restrict__ Alo,
              const __nv_bfloat16* __restrict__ Bhi, const __nv_bfloat16* __restrict__ Blo,
              const float* __restrict__ bias,
              __nv_bfloat16* __restrict__ Chi, __nv_bfloat16* __restrict__ Clo,
              float* __restrict__ Cf, int M, int N, int K)
{
    extern __shared__ char dsm[];
    const uint32_t sb = smem_u32(dsm);

    const int tid = threadIdx.x, lane = tid & 31, wid = tid >> 5;
    const int wm = wid >> 2, wn = wid & 3;
    const int bn = blockIdx.x, bm = blockIdx.y;

    float acc[4][4][4];
#pragma unroll
    for (int i = 0; i < 4; i++)
#pragma unroll
        for (int j = 0; j < 4; j++)
#pragma unroll
            for (int q = 0; q < 4; q++) acc[i][j][q] = 0.f;

    const __nv_bfloat16* srcs[4] = {
        Ahi + (size_t)(bm * 128) * K, Alo + (size_t)(bm * 128) * K,
        Bhi + (size_t)(bn * 128) * K, Blo + (size_t)(bn * 128) * K };

    const int frow = lane >> 2;
    const int fcol = (lane & 3) * 2;

    int stage = 0;
#pragma unroll
    for (int it = 0; it < 8; it++) {
        const int id = tid + it * 256;
        const int tile = id >> 9, rem = id & 511, row = rem >> 2, ch = rem & 3;
        cp16(sb + tile * TILE_B + row * ROWB + ch * 16,
             srcs[tile] + (size_t)row * K + ch * 8);
    }
    asm volatile("cp.async.commit_group;" ::: "memory");

    for (int k0 = 0; k0 < K; k0 += 32) {
        if (k0 + 32 < K) {
            const int nb = (stage ^ 1) * STAGE_B;
#pragma unroll
            for (int it = 0; it < 8; it++) {
                const int id = tid + it * 256;
                const int tile = id >> 9, rem = id & 511, row = rem >> 2, ch = rem & 3;
                cp16(sb + nb + tile * TILE_B + row * ROWB + ch * 16,
                     srcs[tile] + (size_t)row * K + k0 + 32 + ch * 8);
            }
            asm volatile("cp.async.commit_group;" ::: "memory");
            asm volatile("cp.async.wait_group 1;" ::: "memory");
        } else {
            asm volatile("cp.async.wait_group 0;" ::: "memory");
        }
        __syncthreads();

        const __nv_bfloat16* sAh = (const __nv_bfloat16*)(dsm + stage * STAGE_B);
        const __nv_bfloat16* sAl = sAh + 128 * PADK;
        const __nv_bfloat16* sBh = sAl + 128 * PADK;
        const __nv_bfloat16* sBl = sBh + 128 * PADK;

#pragma unroll
        for (int ks = 0; ks < 2; ks++) {
            const int kb = ks * 16 + fcol;
            uint32_t Afh[4][4], Afl[4][4], Bfh[4][2], Bfl[4][2];
#pragma unroll
            for (int mt = 0; mt < 4; mt++) {
                const int r0 = (wm * 64 + mt * 16 + frow) * PADK + kb;
                const int r1 = r0 + 8 * PADK;
                Afh[mt][0] = *(const uint32_t*)(sAh + r0);
                Afh[mt][1] = *(const uint32_t*)(sAh + r1);
                Afh[mt][2] = *(const uint32_t*)(sAh + r0 + 8);
                Afh[mt][3] = *(const uint32_t*)(sAh + r1 + 8);
                Afl[mt][0] = *(const uint32_t*)(sAl + r0);
                Afl[mt][1] = *(const uint32_t*)(sAl + r1);
                Afl[mt][2] = *(const uint32_t*)(sAl + r0 + 8);
                Afl[mt][3] = *(const uint32_t*)(sAl + r1 + 8);
            }
#pragma unroll
            for (int nt = 0; nt < 4; nt++) {
                const int n0 = (wn * 32 + nt * 8 + frow) * PADK + kb;
                Bfh[nt][0] = *(const uint32_t*)(sBh + n0);
                Bfh[nt][1] = *(const uint32_t*)(sBh + n0 + 8);
                Bfl[nt][0] = *(const uint32_t*)(sBl + n0);
                Bfl[nt][1] = *(const uint32_t*)(sBl + n0 + 8);
            }
#pragma unroll
            for (int mt = 0; mt < 4; mt++)
#pragma unroll
                for (int nt = 0; nt < 4; nt++) {
                    float* d = acc[mt][nt];
                    asm volatile(
                        "mma.sync.aligned.m16n8k16.row.col.f32.bf16.bf16.f32 "
                        "{%0,%1,%2,%3}, {%4,%5,%6,%7}, {%8,%9}, {%0,%1,%2,%3};"
                        : "+f"(d[0]), "+f"(d[1]), "+f"(d[2]), "+f"(d[3])
                        : "r"(Afh[mt][0]), "r"(Afh[mt][1]), "r"(Afh[mt][2]), "r"(Afh[mt][3]),
                          "r"(Bfh[nt][0]), "r"(Bfh[nt][1]));
                    asm volatile(
                        "mma.sync.aligned.m16n8k16.row.col.f32.bf16.bf16.f32 "
                        "{%0,%1,%2,%3}, {%4,%5,%6,%7}, {%8,%9}, {%0,%1,%2,%3};"
                        : "+f"(d[0]), "+f"(d[1]), "+f"(d[2]), "+f"(d[3])
                        : "r"(Afh[mt][0]), "r"(Afh[mt][1]), "r"(Afh[mt][2]), "r"(Afh[mt][3]),
                          "r"(Bfl[nt][0]), "r"(Bfl[nt][1]));
                    asm volatile(
                        "mma.sync.aligned.m16n8k16.row.col.f32.bf16.bf16.f32 "
                        "{%0,%1,%2,%3}, {%4,%5,%6,%7}, {%8,%9}, {%0,%1,%2,%3};"
                        : "+f"(d[0]), "+f"(d[1]), "+f"(d[2]), "+f"(d[3])
                        : "r"(Afl[mt][0]), "r"(Afl[mt][1]), "r"(Afl[mt][2]), "r"(Afl[mt][3]),
                          "r"(Bfh[nt][0]), "r"(Bfh[nt][1]));
                }
        }
        __syncthreads();
        stage ^= 1;
    }

#pragma unroll
    for (int mt = 0; mt < 4; mt++) {
        const int rA = bm * 128 + wm * 64 + mt * 16 + frow;
        const int rB = rA + 8;
#pragma unroll
        for (int nt = 0; nt < 4; nt++) {
            const int c = bn * 128 + wn * 32 + nt * 8 + fcol;
            float v00 = acc[mt][nt][0] + bias[c];
            float v01 = acc[mt][nt][1] + bias[c + 1];
            float v10 = acc[mt][nt][2] + bias[c];
            float v11 = acc[mt][nt][3] + bias[c + 1];
            if (ACT == 1) {
                v00 = fmaxf(v00, 0.f); v01 = fmaxf(v01, 0.f);
                v10 = fmaxf(v10, 0.f); v11 = fmaxf(v11, 0.f);
            } else if (ACT == 2) {
                v00 = tanhf(v00); v01 = tanhf(v01);
                v10 = tanhf(v10); v11 = tanhf(v11);
            }
            if (OUT == 2) {
                __nv_bfloat16 h0, l0, h1, l1;
                split_bf16(v00, h0, l0); split_bf16(v01, h1, l1);
                uint32_t hp = (uint32_t)__bfloat16_as_ushort(h0) |
                              ((uint32_t)__bfloat16_as_ushort(h1) << 16);
                uint32_t lp = (uint32_t)__bfloat16_as_ushort(l0) |
                              ((uint32_t)__bfloat16_as_ushort(l1) << 16);
                *(uint32_t*)(Chi + (size_t)rA * N + c) = hp;
                *(uint32_t*)(Clo + (size_t)rA * N + c) = lp;
                split_bf16(v10, h0, l0); split_bf16(v11, h1, l1);
                hp = (uint32_t)__bfloat16_as_ushort(h0) |
                     ((uint32_t)__bfloat16_as_ushort(h1) << 16);
                lp = (uint32_t)__bfloat16_as_ushort(l0) |
                     ((uint32_t)__bfloat16_as_ushort(l1) << 16);
                *(uint32_t*)(Chi + (size_t)rB * N + c) = hp;
                *(uint32_t*)(Clo + (size_t)rB * N + c) = lp;
            } else if (OUT == 1) {
                const int bA = rA >> 9, tA = rA & (T_ - 1);
                const int bB = rB >> 9, tB = rB & (T_ - 1);
                *(float2*)(Cf + (size_t)(tA * B_ + bA) * N + c) = make_float2(v00, v01);
                *(float2*)(Cf + (size_t)(tB * B_ + bB) * N + c) = make_float2(v10, v11);
            } else {
                *(float2*)(Cf + (size_t)rA * N + c) = make_float2(v00, v01);
                *(float2*)(Cf + (size_t)rB * N + c) = make_float2(v10, v11);
            }
        }
    }
}

// ---------------------------------------------------------------------------
// Phase B: persistent recurrence — R10 protocol UNCHANGED, weights now FP16.
// 128 CTAs x 256 threads, clusters of 4, multicast stream, paired chunks.
// Chunk = 8192 halfs = 16 KB (was 32 KB fp32) -> smem crossbar traffic halves.
// Schedule per step (64 chunks x 8192 halfs):
//   chunks  0..15 : W1 rows [16j,16j+16) x 512
//   chunks 16..47 : W2 rows [16j,16j+16) x 512
//   chunks 48..63 : W3 rows [32j,32j+32) x 256
// ---------------------------------------------------------------------------
#define NSTAGE      4
#define CHUNK_H     8192                 // halfs per chunk
#define CHUNK_BYTES (CHUNK_H * 2)        // 16384
#define CHUNKS_PER_STEP 64
#define TOTAL_CHUNKS    (T_ * CHUNKS_PER_STEP)
#define MC_MASK     0xFu

// smem layout in floats
#define SM_WBUF  0                               // NSTAGE*CHUNK_H halfs = 16384 floats
#define SM_HT    (NSTAGE * CHUNK_H / 2)
#define SM_Y1T   (SM_HT + H_ * 2)
#define SM_Y2T   (SM_Y1T + W1_ * 2)
#define SM_B1    (SM_Y2T + W2_ * 2)
#define SM_B2    (SM_B1 + W1_)
#define SM_B3    (SM_B2 + W2_)
#define SM_FULL  (SM_B3 + H_)
#define SM_EMPTY (SM_FULL + 2 * NSTAGE)
#define SMEM_FLOATS (SM_EMPTY + 2 * NSTAGE)
#define SMEM_BYTES  (SMEM_FLOATS * 4)

struct WSrc { const __half* w1; const __half* w2; const __half* w3; };

__device__ __forceinline__ const __half* chunk_src(const WSrc& w, int cg) {
    int c = cg & (CHUNKS_PER_STEP - 1);
    if (c < 16)      return w.w1 + (size_t)c * 16 * W1_;
    else if (c < 48) return w.w2 + (size_t)(c - 16) * 16 * W2_;
    else             return w.w3 + (size_t)(c - 48) * 32 * H_;
}

__global__ void __launch_bounds__(256, 1) __cluster_dims__(4, 1, 1)
recurrence_kernel(const __half* __restrict__ w1, const float* __restrict__ b1,
                  const __half* __restrict__ w2, const float* __restrict__ b2,
                  const __half* __restrict__ w3, const float* __restrict__ b3,
                  const float* __restrict__ xin, float* __restrict__ hs)
{
    extern __shared__ float smemf[];
    __half* wbuf = (__half*)(smemf + SM_WBUF);
    float* hT   = smemf + SM_HT;
    float* y1T  = smemf + SM_Y1T;
    float* y2T  = smemf + SM_Y2T;
    float* bs1  = smemf + SM_B1;
    float* bs2  = smemf + SM_B2;
    float* bs3  = smemf + SM_B3;
    const uint32_t fullb  = smem_u32(smemf + SM_FULL);
    const uint32_t emptyb = smem_u32(smemf + SM_EMPTY);

    const int tid = threadIdx.x;
    const int b0  = blockIdx.x * 2;
    const uint32_t rank = cluster_rank();
    WSrc wsrc = { w1, w2, w3 };

    for (int i = tid; i < W1_; i += 256) bs1[i] = b1[i];
    for (int i = tid; i < W2_; i += 256) bs2[i] = b2[i];
    for (int i = tid; i < H_;  i += 256) bs3[i] = b3[i];
    for (int i = tid; i < H_ * 2; i += 256) hT[i] = 0.f;
    if (tid == 0) {
#pragma unroll
        for (int s = 0; s < NSTAGE; s++) {
            mbar_init(fullb  + s * 8, 1);
            mbar_init(emptyb + s * 8, NSTAGE);
        }
    }
    __syncthreads();

    if (tid == 0) {
#pragma unroll
        for (int s = 0; s < NSTAGE; s++) mbar_expect_tx(fullb + s * 8, CHUNK_BYTES);
    }
    CLUSTER_SYNC();
    if (tid == 0) {
        bulk_g2s_mc(smem_u32(wbuf + rank * CHUNK_H), chunk_src(wsrc, (int)rank),
                    CHUNK_BYTES, fullb + rank * 8, MC_MASK);
    }

    int chunk = 0;

#define PAIR_BOOKKEEP()                                                         \
    do {                                                                        \
        __syncthreads();                                                        \
        if (tid == 0) {                                                         \
            _Pragma("unroll")                                                   \
            for (int q = 0; q < 2; q++) {                                       \
                const int cq = chunk + q;                                       \
                if (cq + NSTAGE < TOTAL_CHUNKS) {                               \
                    const int s_ = cq & (NSTAGE - 1);                           \
                    mbar_expect_tx(fullb + s_ * 8, CHUNK_BYTES);                \
                    mbar_arrive_remote(mapa_rank(emptyb + s_ * 8, (uint32_t)s_));\
                    if (rank == (uint32_t)s_) {                                 \
                        mbar_wait_parity(emptyb + s_ * 8, (cq >> 2) & 1);       \
                        bulk_g2s_mc(smem_u32(wbuf + s_ * CHUNK_H),              \
                                    chunk_src(wsrc, cq + NSTAGE),               \
                                    CHUNK_BYTES, fullb + s_ * 8, MC_MASK);      \
                    }                                                           \
                }                                                               \
            }                                                                   \
        }                                                                       \
        chunk += 2;                                                             \
    } while (0)

    for (int t = 0; t < T_; t++) {
        const int c0 = tid * 2;

        {   // Layer 1: K=256, 8 pairs
            u64 a0 = 0, a1 = 0;
            for (int jp = 0; jp < 8; jp++) {
                const int s0 = chunk & (NSTAGE - 1);
                const int s1 = (chunk + 1) & (NSTAGE - 1);
                mbar_wait_parity(fullb + s0 * 8, (chunk >> 2) & 1);
                mbar_wait_parity(fullb + s1 * 8, ((chunk + 1) >> 2) & 1);
                const __half* wb0 = wbuf + s0 * CHUNK_H;
                const __half* wb1 = wbuf + s1 * CHUNK_H;
#pragma unroll
                for (int kk = 0; kk < 16; kk++) {
                    const int k = jp * 32 + kk;
                    u64 r = *(const u64*)(hT + k * 2);
                    float2 w = __half22float2(*(const __half2*)(wb0 + kk * W1_ + c0));
                    a0 = fma2(r, dup2(w.x), a0);
                    a1 = fma2(r, dup2(w.y), a1);
                }
#pragma unroll
                for (int kk = 0; kk < 16; kk++) {
                    const int k = jp * 32 + 16 + kk;
                    u64 r = *(const u64*)(hT + k * 2);
                    float2 w = __half22float2(*(const __half2*)(wb1 + kk * W1_ + c0));
                    a0 = fma2(r, dup2(w.x), a0);
                    a1 = fma2(r, dup2(w.y), a1);
                }
                PAIR_BOOKKEEP();
            }
            float v0, v1;
            const float bb0 = bs1[c0], bb1 = bs1[c0 + 1];
            unpack2(a0, v0, v1);
            *(float2*)(y1T + c0 * 2) =
                make_float2(fmaxf(v0 + bb0, 0.f), fmaxf(v1 + bb0, 0.f));
            unpack2(a1, v0, v1);
            *(float2*)(y1T + (c0 + 1) * 2) =
                make_float2(fmaxf(v0 + bb1, 0.f), fmaxf(v1 + bb1, 0.f));
        }
        __syncthreads();

        {   // Layer 2: K=512, 16 pairs
            u64 a0 = 0, a1 = 0;
            for (int jp = 0; jp < 16; jp++) {
                const int s0 = chunk & (NSTAGE - 1);
                const int s1 = (chunk + 1) & (NSTAGE - 1);
                mbar_wait_parity(fullb + s0 * 8, (chunk >> 2) & 1);
                mbar_wait_parity(fullb + s1 * 8, ((chunk + 1) >> 2) & 1);
                const __half* wb0 = wbuf + s0 * CHUNK_H;
                const __half* wb1 = wbuf + s1 * CHUNK_H;
#pragma unroll
                for (int kk = 0; kk < 16; kk++) {
                    const int k = jp * 32 + kk;
                    u64 r = *(const u64*)(y1T + k * 2);
                    float2 w = __half22float2(*(const __half2*)(wb0 + kk * W2_ + c0));
                    a0 = fma2(r, dup2(w.x), a0);
                    a1 = fma2(r, dup2(w.y), a1);
                }
#pragma unroll
                for (int kk = 0; kk < 16; kk++) {
                    const int k = jp * 32 + 16 + kk;
                    u64 r = *(const u64*)(y1T + k * 2);
                    float2 w = __half22float2(*(const __half2*)(wb1 + kk * W2_ + c0));
                    a0 = fma2(r, dup2(w.x), a0);
                    a1 = fma2(r, dup2(w.y), a1);
                }
                PAIR_BOOKKEEP();
            }
            float v0, v1;
            const float bb0 = bs2[c0], bb1 = bs2[c0 + 1];
            unpack2(a0, v0, v1);
            *(float2*)(y2T + c0 * 2) =
                make_float2(fmaxf(v0 + bb0, 0.f), fmaxf(v1 + bb0, 0.f));
            unpack2(a1, v0, v1);
            *(float2*)(y2T + (c0 + 1) * 2) =
                make_float2(fmaxf(v0 + bb1, 0.f), fmaxf(v1 + bb1, 0.f));
        }
        __syncthreads();

        {   // Layer 3: K=512, 8 pairs (64 k per pair)
            const int c = tid;
            u64 ae = 0, ao = 0;
            for (int jp = 0; jp < 8; jp++) {
                const int s0 = chunk & (NSTAGE - 1);
                const int s1 = (chunk + 1) & (NSTAGE - 1);
                mbar_wait_parity(fullb + s0 * 8, (chunk >> 2) & 1);
                mbar_wait_parity(fullb + s1 * 8, ((chunk + 1) >> 2) & 1);
                const __half* wb0 = wbuf + s0 * CHUNK_H;
                const __half* wb1 = wbuf + s1 * CHUNK_H;
#pragma unroll
                for (int kk = 0; kk < 32; kk += 2) {
                    const int k = jp * 64 + kk;
                    u64 r0 = *(const u64*)(y2T + k * 2);
                    u64 r1 = *(const u64*)(y2T + (k + 1) * 2);
                    ae = fma2(r0, dup2(__half2float(wb0[kk * H_ + c])),       ae);
                    ao = fma2(r1, dup2(__half2float(wb0[(kk + 1) * H_ + c])), ao);
                }
#pragma unroll
                for (int kk = 0; kk < 32; kk += 2) {
                    const int k = jp * 64 + 32 + kk;
                    u64 r0 = *(const u64*)(y2T + k * 2);
                    u64 r1 = *(const u64*)(y2T + (k + 1) * 2);
                    ae = fma2(r0, dup2(__half2float(wb1[kk * H_ + c])),       ae);
                    ao = fma2(r1, dup2(__half2float(wb1[(kk + 1) * H_ + c])), ao);
                }
                PAIR_BOOKKEEP();
            }
            float e0, e1, o0, o1;
            unpack2(ae, e0, e1); unpack2(ao, o0, o1);
            const float bb = bs3[c];
            const float* xr = xin + (size_t)t * B_ * H_ + (size_t)b0 * H_ + c;
            float*       hr = hs  + (size_t)t * B_ * H_ + (size_t)b0 * H_ + c;
            float v0 = tanhf(e0 + o0 + bb + xr[0 * H_]);
            float v1 = tanhf(e1 + o1 + bb + xr[1 * H_]);
            hr[0 * H_] = v0; hr[1 * H_] = v1;
            *(float2*)(hT + c * 2) = make_float2(v0, v1);
        }
        __syncthreads();
    }

    CLUSTER_SYNC();
#undef PAIR_BOOKKEEP
}

// ---------------------------------------------------------------------------
// Phase C reduction: online softmax over T (axis 0) + weighted sum of hs.
// ---------------------------------------------------------------------------
__global__ void attn_reduce_kernel(const float* __restrict__ aw,
                                   const float* __restrict__ hs,
                                   float* __restrict__ out)
{
    const int b = blockIdx.x;
    const int h = threadIdx.x;
    float m = -1e30f, s = 0.f, acc = 0.f;
    for (int t = 0; t < T_; t++) {
        size_t idx = ((size_t)t * B_ + b) * H_ + h;
        float a  = aw[idx];
        float hv = hs[idx];
        if (a > m) {
            float c = __expf(m - a);
            s   = s * c + 1.f;
            acc = acc * c + hv;
            m   = a;
        } else {
            float e = __expf(a - m);
            s   += e;
            acc += e * hv;
        }
    }
    out[(size_t)b * H_ + h] = acc / s;
}

// ---------------------------------------------------------------------------
// Launch
// ---------------------------------------------------------------------------
extern "C" void kernel_launch(void* const* d_in, const int* in_sizes, int n_in,
                              void* d_out, int out_size)
{
    const float* x     = (const float*)d_in[0];
    const float* h_w1  = (const float*)d_in[1];
    const float* h_b1  = (const float*)d_in[2];
    const float* h_w2  = (const float*)d_in[3];
    const float* h_b2  = (const float*)d_in[4];
    const float* h_w3  = (const float*)d_in[5];
    const float* h_b3  = (const float*)d_in[6];
    const float* i_w1  = (const float*)d_in[7];
    const float* i_b1  = (const float*)d_in[8];
    const float* i_w2  = (const float*)d_in[9];
    const float* i_b2  = (const float*)d_in[10];
    const float* i_w3  = (const float*)d_in[11];
    const float* i_b3  = (const float*)d_in[12];
    const float* att_w = (const float*)d_in[13];
    const float* att_b = (const float*)d_in[14];
    float* out = (float*)d_out;

    float *aw, *xin, *hs;
    cudaGetSymbolAddress((void**)&aw,  g_aw);
    cudaGetSymbolAddress((void**)&xin, g_xin);
    cudaGetSymbolAddress((void**)&hs,  g_hs);
    __nv_bfloat16 *xhi, *xlo, *a1hi, *a1lo, *a2hi, *a2lo;
    __nv_bfloat16 *w1Thi, *w1Tlo, *w2Thi, *w2Tlo, *w3Thi, *w3Tlo;
    cudaGetSymbolAddress((void**)&xhi,  g_xhi);  cudaGetSymbolAddress((void**)&xlo,  g_xlo);
    cudaGetSymbolAddress((void**)&a1hi, g_a1hi); cudaGetSymbolAddress((void**)&a1lo, g_a1lo);
    cudaGetSymbolAddress((void**)&a2hi, g_a2hi); cudaGetSymbolAddress((void**)&a2lo, g_a2lo);
    cudaGetSymbolAddress((void**)&w1Thi, g_w1Thi); cudaGetSymbolAddress((void**)&w1Tlo, g_w1Tlo);
    cudaGetSymbolAddress((void**)&w2Thi, g_w2Thi); cudaGetSymbolAddress((void**)&w2Tlo, g_w2Tlo);
    cudaGetSymbolAddress((void**)&w3Thi, g_w3Thi); cudaGetSymbolAddress((void**)&w3Tlo, g_w3Tlo);
    __half *w1h, *w2h, *w3h;
    cudaGetSymbolAddress((void**)&w1h, g_w1h);
    cudaGetSymbolAddress((void**)&w2h, g_w2h);
    cudaGetSymbolAddress((void**)&w3h, g_w3h);

    cudaFuncSetAttribute(mm_mma_kernel<1, 2>,
                         cudaFuncAttributeMaxDynamicSharedMemorySize, MMA_SMEM);
    cudaFuncSetAttribute(mm_mma_kernel<0, 1>,
                         cudaFuncAttributeMaxDynamicSharedMemorySize, MMA_SMEM);
    cudaFuncSetAttribute(mm_mma_kernel<2, 0>,
                         cudaFuncAttributeMaxDynamicSharedMemorySize, MMA_SMEM);

    // ---------------- Phase A: bf16-split mma.sync input MLP --------------
    split_kernel<<<(BT_ * IN_) / 1024, 256>>>(x, xhi, xlo, BT_ * IN_);
    splitT_kernel<<<(IN_ * W1_) / 256, 256>>>(i_w1, w1Thi, w1Tlo, IN_, W1_);
    splitT_kernel<<<(W1_ * W2_) / 256, 256>>>(i_w2, w2Thi, w2Tlo, W1_, W2_);
    splitT_kernel<<<(W2_ * H_)  / 256, 256>>>(i_w3, w3Thi, w3Tlo, W2_, H_);
    // fp16 recurrence weights (Phase B)
    to_half_kernel<<<(H_ * W1_)  / 1024, 256>>>(h_w1, w1h, H_ * W1_);
    to_half_kernel<<<(W1_ * W2_) / 1024, 256>>>(h_w2, w2h, W1_ * W2_);
    to_half_kernel<<<(W2_ * H_)  / 1024, 256>>>(h_w3, w3h, W2_ * H_);

    mm_mma_kernel<1, 2><<<dim3(W1_ / 128, BT_ / 128), 256, MMA_SMEM>>>(
        xhi, xlo, w1Thi, w1Tlo, i_b1, a1hi, a1lo, nullptr, BT_, W1_, IN_);
    mm_mma_kernel<1, 2><<<dim3(W2_ / 128, BT_ / 128), 256, MMA_SMEM>>>(
        a1hi, a1lo, w2Thi, w2Tlo, i_b2, a2hi, a2lo, nullptr, BT_, W2_, W1_);
    mm_mma_kernel<0, 1><<<dim3(H_ / 128, BT_ / 128), 256, MMA_SMEM>>>(
        a2hi, a2lo, w3Thi, w3Tlo, i_b3, nullptr, nullptr, xin, BT_, H_, W2_);

    // ---------------- Phase B: persistent recurrence (ONE launch) ---------
    cudaFuncSetAttribute(recurrence_kernel,
                         cudaFuncAttributeMaxDynamicSharedMemorySize, SMEM_BYTES);
    recurrence_kernel<<<128, 256, SMEM_BYTES>>>(
        w1h, h_b1, w2h, h_b2, w3h, h_b3, xin, hs);

    // ---------------- Phase C: attention pooling (tensor path) ------------
    split_kernel<<<(BT_ * H_) / 1024, 256>>>(hs, a2hi, a2lo, BT_ * H_);
    splitT_kernel<<<(H_ * H_) / 256, 256>>>(att_w, w1Thi, w1Tlo, H_, H_);
    mm_mma_kernel<2, 0><<<dim3(H_ / 128, BT_ / 128), 256, MMA_SMEM>>>(
        a2hi, a2lo, w1Thi, w1Tlo, att_b, nullptr, nullptr, aw, BT_, H_, H_);
    attn_reduce_kernel<<<B_, H_>>>(aw, hs, out);
}